// round 15
// baseline (speedup 1.0000x reference)
#include <cuda_runtime.h>
#include <cuda_fp16.h>
#include <cstdint>

#define N_NODES 100000
#define E_MAX   1600000
#define NPART   98          // ceil(100000/1024)
#define XQUADS  (N_NODES * 16)   // x as float4: 100000*64/4 = 1.6M
#define NT      782              // M tiles of 128

// ---------------- device scratch (static; zero-init, no dynamic allocation) -----
__device__ int    g_is64;
__device__ int    g_deg[N_NODES];        // zeroed by scatter (prev call) / static
__device__ int    g_offs[N_NODES + 1];
__device__ int    g_cursor[N_NODES];
__device__ int    g_blk_total[NPART];
__device__ int    g_blk_flag[NPART];     // zeroed by scatter (prev call) / static
__device__ int    g_src_sorted[E_MAX];
__device__ __half g_x16[(size_t)N_NODES * 64];    // fp16 copy of x
// fp16 operands:  A1 = [agg1 | x] (stride 128),  A2 = [agg2 | h] (stride 256)
__device__ __half g_A1[(size_t)N_NODES * 128];
__device__ __half g_A2[(size_t)N_NODES * 256];
__device__ __half g_w1[128 * 128];    // [n][k] concat(W1l, W1r)
__device__ __half g_w2[128 * 256];    // [n][k] concat(W2l, W2r)

// ==================== PTX helpers (family-portable) ====================
__device__ __forceinline__ uint32_t smem_u32(const void* p) {
    uint32_t a;
    asm("{ .reg .u64 t; cvta.to.shared.u64 t, %1; cvt.u32.u64 %0, t; }" : "=r"(a) : "l"(p));
    return a;
}
#define LDSM_X4(r0, r1, r2, r3, addr)                                           \
    asm volatile("ldmatrix.sync.aligned.m8n8.x4.shared.b16 {%0,%1,%2,%3}, [%4];" \
                 : "=r"(r0), "=r"(r1), "=r"(r2), "=r"(r3) : "r"(addr))
#define MMA16816F(c, a, b)                                                       \
    asm volatile("mma.sync.aligned.m16n8k16.row.col.f32.f16.f16.f32 "            \
                 "{%0,%1,%2,%3}, {%4,%5,%6,%7}, {%8,%9}, {%0,%1,%2,%3};"         \
                 : "+f"((c)[0]), "+f"((c)[1]), "+f"((c)[2]), "+f"((c)[3])        \
                 : "r"((a)[0]), "r"((a)[1]), "r"((a)[2]), "r"((a)[3]),           \
                   "r"((b)[0]), "r"((b)[1]))
__device__ __forceinline__ void cp16(uint32_t dst, const void* src) {
    asm volatile("cp.async.cg.shared.global [%0], [%1], 16;" :: "r"(dst), "l"(src));
}
#define CP_COMMIT() asm volatile("cp.async.commit_group;" ::: "memory")
#define CP_WAIT1()  asm volatile("cp.async.wait_group 1;" ::: "memory")
#define CP_WAIT0()  asm volatile("cp.async.wait_group 0;" ::: "memory")

__device__ __forceinline__ uint32_t pack_h2(float a, float b) {
    __half2 h = __floats2half2_rn(a, b);
    return *(uint32_t*)&h;
}
__device__ __forceinline__ __half2 u2h(uint32_t u) { return *(__half2*)&u; }
// exact fp32 accumulate of one row (remainders)
__device__ __forceinline__ void acc8(const uint4& p, float* a) {
    float2 f0 = __half22float2(u2h(p.x));
    float2 f1 = __half22float2(u2h(p.y));
    float2 f2 = __half22float2(u2h(p.z));
    float2 f3 = __half22float2(u2h(p.w));
    a[0] += f0.x; a[1] += f0.y; a[2] += f1.x; a[3] += f1.y;
    a[4] += f2.x; a[5] += f2.y; a[6] += f3.x; a[7] += f3.y;
}
// fp16 pairwise tree over 4 rows, fp32 flush
__device__ __forceinline__ void acc8_tree4(const uint4& p0, const uint4& p1,
                                           const uint4& p2, const uint4& p3, float* a) {
    __half2 t; float2 f;
    t = __hadd2(__hadd2(u2h(p0.x), u2h(p1.x)), __hadd2(u2h(p2.x), u2h(p3.x)));
    f = __half22float2(t); a[0] += f.x; a[1] += f.y;
    t = __hadd2(__hadd2(u2h(p0.y), u2h(p1.y)), __hadd2(u2h(p2.y), u2h(p3.y)));
    f = __half22float2(t); a[2] += f.x; a[3] += f.y;
    t = __hadd2(__hadd2(u2h(p0.z), u2h(p1.z)), __hadd2(u2h(p2.z), u2h(p3.z)));
    f = __half22float2(t); a[4] += f.x; a[5] += f.y;
    t = __hadd2(__hadd2(u2h(p0.w), u2h(p1.w)), __hadd2(u2h(p2.w), u2h(p3.w)));
    f = __half22float2(t); a[6] += f.x; a[7] += f.y;
}
// fp16 pairwise tree over 8 rows, fp32 flush
__device__ __forceinline__ void acc8_tree8(const uint4* p, float* a) {
#pragma unroll
    for (int wd = 0; wd < 4; wd++) {
        uint32_t q0 = (&p[0].x)[wd], q1 = (&p[1].x)[wd], q2 = (&p[2].x)[wd], q3 = (&p[3].x)[wd];
        uint32_t q4 = (&p[4].x)[wd], q5 = (&p[5].x)[wd], q6 = (&p[6].x)[wd], q7 = (&p[7].x)[wd];
        __half2 t = __hadd2(
            __hadd2(__hadd2(u2h(q0), u2h(q1)), __hadd2(u2h(q2), u2h(q3))),
            __hadd2(__hadd2(u2h(q4), u2h(q5)), __hadd2(u2h(q6), u2h(q7))));
        float2 f = __half22float2(t);
        a[2 * wd] += f.x; a[2 * wd + 1] += f.y;
    }
}

// ==================== launch 0: init (detect + weights + x->fp16 + HIST) ========
__global__ void init_kernel(const void* __restrict__ ei, const int* __restrict__ ei32,
                            int n_words, int E,
                            const float* __restrict__ x,
                            const float* __restrict__ W1l, const float* __restrict__ W1r,
                            const float* __restrict__ W2l, const float* __restrict__ W2r) {
    __shared__ int s_is64;
    int idx = blockIdx.x * blockDim.x + threadIdx.x;
    if (threadIdx.x < 32) {
        int lane = threadIdx.x;
        int wi = 1 + 2 * lane;
        int z = (wi < n_words && ei32[wi] == 0) ? 1 : 0;
        unsigned m = __ballot_sync(0xffffffffu, z);
        if (lane == 0) {
            s_is64 = (__popc(m) > 24) ? 1 : 0;
            if (blockIdx.x == 0) g_is64 = s_is64;
        }
    }
    __syncthreads();
    int is64 = s_is64;
    if (idx < E) {
        int d = is64 ? (int)((const long long*)ei)[(size_t)E + idx]
                     : ((const int*)ei)[(size_t)E + idx];
        if ((unsigned)d < (unsigned)N_NODES) atomicAdd(&g_deg[d], 1);
    }
    if (idx < 128 * 128) {                       // layer 1 weights: Ktot=128, Kh=64
        int n = idx >> 7, k = idx & 127;
        float v = (k < 64) ? W1l[n * 64 + k] : W1r[n * 64 + (k - 64)];
        g_w1[idx] = __float2half_rn(v);
    } else if (idx < 128 * 128 + 128 * 256) {    // layer 2 weights: Ktot=256, Kh=128
        int j = idx - 128 * 128;
        int n = j >> 8, k = j & 255;
        float v = (k < 128) ? W2l[n * 128 + k] : W2r[n * 128 + (k - 128)];
        g_w2[j] = __float2half_rn(v);
    }
    if (idx < XQUADS) {                          // x -> fp16 (per float4)
        float4 v = *(const float4*)&x[(size_t)idx * 4];
        uint2 o;
        o.x = pack_h2(v.x, v.y);
        o.y = pack_h2(v.z, v.w);
        *(uint2*)&g_x16[(size_t)idx * 4] = o;
    }
}

// ==================== launch 1: single-pass scan (decoupled lookback) ===========
__global__ void scan_kernel() {
    __shared__ int s_woff[32];
    __shared__ int s_red[4];
    __shared__ int s_pred;
    int tid = threadIdx.x, lane = tid & 31, wid = tid >> 5;
    int bid = blockIdx.x;
    int i = bid * 1024 + tid;
    int v = (i < N_NODES) ? g_deg[i] : 0;
    int inc = v;
#pragma unroll
    for (int o = 1; o < 32; o <<= 1) {
        int t = __shfl_up_sync(0xffffffffu, inc, o);
        if (lane >= o) inc += t;
    }
    if (lane == 31) s_woff[wid] = inc;
    __syncthreads();
    if (wid == 0) {
        int ws = s_woff[lane];
        int wi = ws;
#pragma unroll
        for (int o = 1; o < 32; o <<= 1) {
            int t = __shfl_up_sync(0xffffffffu, wi, o);
            if (lane >= o) wi += t;
        }
        s_woff[lane] = wi - ws;
    }
    __syncthreads();
    int excl = s_woff[wid] + inc - v;
    if (tid == 1023) {
        g_blk_total[bid] = excl + v;
        __threadfence();
        atomicExch(&g_blk_flag[bid], 1);
    }
    int myp = 0;
    if (tid < bid) {
        while (atomicAdd(&g_blk_flag[tid], 0) == 0) {}
        myp = atomicAdd(&g_blk_total[tid], 0);
    }
    if (tid < 128) {
#pragma unroll
        for (int o = 16; o > 0; o >>= 1)
            myp += __shfl_xor_sync(0xffffffffu, myp, o);
        if (lane == 0) s_red[wid] = myp;
    }
    __syncthreads();
    if (tid == 0) s_pred = s_red[0] + s_red[1] + s_red[2] + s_red[3];
    __syncthreads();
    int off = s_pred;
    if (i < N_NODES) {
        int o = excl + off;
        g_offs[i] = o;
        g_cursor[i] = o;
    }
    if (bid == NPART - 1 && tid == 1023) g_offs[N_NODES] = off + excl + v;
}

// ==================== launch 2: scatter (+ cleanup for next call) ===============
__global__ void scatter_kernel(const void* __restrict__ ei, int E) {
    int e = blockIdx.x * blockDim.x + threadIdx.x;
    int is64 = g_is64;
    if (e < E) {
        int d, s;
        if (is64) {
            d = (int)((const long long*)ei)[(size_t)E + e];
            s = (int)((const long long*)ei)[(size_t)e];
        } else {
            d = ((const int*)ei)[(size_t)E + e];
            s = ((const int*)ei)[(size_t)e];
        }
        if ((unsigned)d < (unsigned)N_NODES && (unsigned)s < (unsigned)N_NODES) {
            int p = atomicAdd(&g_cursor[d], 1);
            g_src_sorted[p] = s;
        }
    }
    if (e < N_NODES) g_deg[e] = 0;
    if (e < NPART) g_blk_flag[e] = 0;
}

// ==================== aggregation: node-per-group, unroll-8 fp16 tree ===========
// agg1: warp = 4 nodes; group of 8 lanes owns one node (lane's 16B = 8 features).
__global__ void agg1_kernel() {
    int gt = blockIdx.x * blockDim.x + threadIdx.x;
    int warp = gt >> 5, lane = threadIdx.x & 31;
    int grp = lane >> 3, gl = lane & 7;
    int w = warp * 4 + grp;
    if (w >= N_NODES) return;
    int beg = g_offs[w], end = g_offs[w + 1];
    float inv = 1.0f / (float)max(end - beg, 1);
    float a[8] = {0.f, 0.f, 0.f, 0.f, 0.f, 0.f, 0.f, 0.f};
    int e = beg;
    for (; e + 7 < end; e += 8) {
        uint4 p[8];
#pragma unroll
        for (int j = 0; j < 8; j++) {
            int ss = g_src_sorted[e + j];
            p[j] = *(const uint4*)&g_x16[(size_t)ss * 64 + gl * 8];
        }
        acc8_tree8(p, a);
    }
    for (; e + 3 < end; e += 4) {
        int s0 = g_src_sorted[e];
        int s1 = g_src_sorted[e + 1];
        int s2 = g_src_sorted[e + 2];
        int s3 = g_src_sorted[e + 3];
        uint4 p0 = *(const uint4*)&g_x16[(size_t)s0 * 64 + gl * 8];
        uint4 p1 = *(const uint4*)&g_x16[(size_t)s1 * 64 + gl * 8];
        uint4 p2 = *(const uint4*)&g_x16[(size_t)s2 * 64 + gl * 8];
        uint4 p3 = *(const uint4*)&g_x16[(size_t)s3 * 64 + gl * 8];
        acc8_tree4(p0, p1, p2, p3, a);
    }
    for (; e < end; e++) {
        int ss = g_src_sorted[e];
        uint4 p = *(const uint4*)&g_x16[(size_t)ss * 64 + gl * 8];
        acc8(p, a);
    }
    uint4 o;
    o.x = pack_h2(a[0] * inv, a[1] * inv);
    o.y = pack_h2(a[2] * inv, a[3] * inv);
    o.z = pack_h2(a[4] * inv, a[5] * inv);
    o.w = pack_h2(a[6] * inv, a[7] * inv);
    *(uint4*)&g_A1[(size_t)w * 128 + gl * 8] = o;
    *(uint4*)&g_A1[(size_t)w * 128 + 64 + gl * 8] =
        *(const uint4*)&g_x16[(size_t)w * 64 + gl * 8];
}
// agg2: warp = 2 nodes; group of 16 lanes owns one node.
__global__ void agg2_kernel() {
    int gt = blockIdx.x * blockDim.x + threadIdx.x;
    int warp = gt >> 5, lane = threadIdx.x & 31;
    int grp = lane >> 4, gl = lane & 15;
    int w = warp * 2 + grp;
    if (w >= N_NODES) return;
    int beg = g_offs[w], end = g_offs[w + 1];
    float inv = 1.0f / (float)max(end - beg, 1);
    float a[8] = {0.f, 0.f, 0.f, 0.f, 0.f, 0.f, 0.f, 0.f};
    int e = beg;
    for (; e + 7 < end; e += 8) {
        uint4 p[8];
#pragma unroll
        for (int j = 0; j < 8; j++) {
            int ss = g_src_sorted[e + j];
            p[j] = *(const uint4*)&g_A2[(size_t)ss * 256 + 128 + gl * 8];
        }
        acc8_tree8(p, a);
    }
    for (; e + 3 < end; e += 4) {
        int s0 = g_src_sorted[e];
        int s1 = g_src_sorted[e + 1];
        int s2 = g_src_sorted[e + 2];
        int s3 = g_src_sorted[e + 3];
        uint4 p0 = *(const uint4*)&g_A2[(size_t)s0 * 256 + 128 + gl * 8];
        uint4 p1 = *(const uint4*)&g_A2[(size_t)s1 * 256 + 128 + gl * 8];
        uint4 p2 = *(const uint4*)&g_A2[(size_t)s2 * 256 + 128 + gl * 8];
        uint4 p3 = *(const uint4*)&g_A2[(size_t)s3 * 256 + 128 + gl * 8];
        acc8_tree4(p0, p1, p2, p3, a);
    }
    for (; e < end; e++) {
        int ss = g_src_sorted[e];
        uint4 p = *(const uint4*)&g_A2[(size_t)ss * 256 + 128 + gl * 8];
        acc8(p, a);
    }
    uint4 o;
    o.x = pack_h2(a[0] * inv, a[1] * inv);
    o.y = pack_h2(a[2] * inv, a[3] * inv);
    o.z = pack_h2(a[4] * inv, a[5] * inv);
    o.w = pack_h2(a[6] * inv, a[7] * inv);
    *(uint4*)&g_A2[(size_t)w * 256 + gl * 8] = o;
}

// ==================== W-resident persistent fp16 mma GEMM (BK=64) ===============
// W lives in smem (row stride KT+8 halves -> ldmatrix rows 4 banks apart, conflict
// free). Persistent CTAs loop over M tiles with an A-only 2-stage cp.async pipe.
template <int KT, bool RELU, int LAYER>
__global__ __launch_bounds__(256) void gemm_fp16_kernel(
    const float* __restrict__ bias, float* __restrict__ out_ext)
{
    constexpr int NCH = KT / 64;                 // BK=64 chunks
    constexpr int WS = KT + 8;                   // W smem row stride (halves)
    constexpr int RS2 = 72;                      // A smem row stride (halves)
    constexpr uint32_t A_STG = 128 * RS2 * 2;    // 18432 B per A stage
    extern __shared__ __align__(16) __half dsm[];
    __half* sW = dsm;
    __half* sA = dsm + 128 * WS;

    const __half* A = (LAYER == 1) ? g_A1 : g_A2;
    const __half* W = (LAYER == 1) ? g_w1 : g_w2;

    const int tid = threadIdx.x, lane = tid & 31, wid = tid >> 5;
    const int wr = wid & 3, wc = wid >> 2;

    // ---- preload W (once per CTA); visibility via first pipeline sync ----
    constexpr int UPR = KT / 8;                  // 16B units per W row
    for (int u = tid; u < 128 * UPR; u += 256) {
        int r = u / UPR, cu = u % UPR;
        *(uint4*)&sW[r * WS + cu * 8] = *(const uint4*)&W[(size_t)r * KT + cu * 8];
    }

    const uint32_t sa0 = smem_u32(sA);
    const uint32_t swb = smem_u32(sW);

    const int ld_r = tid >> 1;
    const int ld_u4 = (tid & 1) * 4;             // this thread's first 16B unit

    const int a_m = ((lane >> 3) & 1) * 8 + (lane & 7);
    const int a_u = (lane >> 4);
    const int b_n = ((lane >> 4) << 3) + (lane & 7);
    const int b_u = ((lane >> 3) & 1);
    const int g = lane >> 2, tg = lane & 3;

    for (int tile = blockIdx.x; tile < NT; tile += gridDim.x) {
        const int row0 = tile * 128;
        const int valid = min(128, N_NODES - row0);
        const int ar = min(row0 + ld_r, N_NODES - 1);
        const size_t goA = (size_t)ar * KT + ld_u4 * 8;
        const uint32_t dst_ru = (uint32_t)(ld_r * RS2 + ld_u4 * 8) * 2;

        float c[2][8][4];
#pragma unroll
        for (int mi = 0; mi < 2; mi++)
#pragma unroll
            for (int ni = 0; ni < 8; ni++)
#pragma unroll
                for (int q = 0; q < 4; q++) c[mi][ni][q] = 0.f;

        __syncthreads();    // previous tile's A-buffer reads done (and W visible)
        {   // prefetch chunk 0 (+1 if present); 4 consecutive 16B units per thread
            uint32_t d = sa0 + dst_ru;
#pragma unroll
            for (int j = 0; j < 4; j++) cp16(d + j * 16, &A[goA + j * 8]);
            CP_COMMIT();
            if (NCH > 1) {
                uint32_t d1 = sa0 + A_STG + dst_ru;
#pragma unroll
                for (int j = 0; j < 4; j++) cp16(d1 + j * 16, &A[goA + 64 + j * 8]);
                CP_COMMIT();
            }
        }

        for (int kc = 0; kc < NCH; kc++) {
            if (kc > 0 && kc + 1 < NCH) {
                uint32_t d = sa0 + ((kc + 1) & 1) * A_STG + dst_ru;
                size_t ko = (size_t)(kc + 1) * 64;
#pragma unroll
                for (int j = 0; j < 4; j++) cp16(d + j * 16, &A[goA + ko + j * 8]);
                CP_COMMIT();
            }
            if (kc + 1 < NCH) CP_WAIT1(); else CP_WAIT0();
            __syncthreads();                      // RAW: buf[kc&1] visible block-wide

            const uint32_t sa = sa0 + (kc & 1) * A_STG;
#pragma unroll
            for (int ks = 0; ks < 4; ks++) {
                uint32_t af[2][4], bf[8][2];
#pragma unroll
                for (int mi = 0; mi < 2; mi++) {
                    int rr = wr * 32 + mi * 16 + a_m;
                    uint32_t off = (uint32_t)(rr * RS2 + ks * 16 + a_u * 8) * 2;
                    LDSM_X4(af[mi][0], af[mi][1], af[mi][2], af[mi][3], sa + off);
                }
#pragma unroll
                for (int nj = 0; nj < 4; nj++) {
                    int nr = wc * 64 + nj * 16 + b_n;
                    uint32_t off = (uint32_t)(nr * WS + kc * 64 + ks * 16 + b_u * 8) * 2;
                    LDSM_X4(bf[nj * 2][0], bf[nj * 2][1], bf[nj * 2 + 1][0], bf[nj * 2 + 1][1], swb + off);
                }
#pragma unroll
                for (int mi = 0; mi < 2; mi++)
#pragma unroll
                    for (int ni = 0; ni < 8; ni++)
                        MMA16816F(c[mi][ni], af[mi], bf[ni]);
            }
            __syncthreads();                      // WAR: reads of buf[kc&1] complete
        }

        // ---- epilogue: bias + (relu); layer1 -> h (fp16) into A2 cols 128..255 ----
#pragma unroll
        for (int ni = 0; ni < 8; ni++) {
            int col = wc * 64 + ni * 8 + tg * 2;
            float2 bv = *(const float2*)&bias[col];
#pragma unroll
            for (int mi = 0; mi < 2; mi++) {
                int rl = wr * 32 + mi * 16 + g;
#pragma unroll
                for (int hrow = 0; hrow < 2; hrow++) {
                    int r = rl + hrow * 8;
                    if (r >= valid) continue;
                    float v0 = c[mi][ni][hrow * 2 + 0] + bv.x;
                    float v1 = c[mi][ni][hrow * 2 + 1] + bv.y;
                    if (RELU) { v0 = fmaxf(v0, 0.f); v1 = fmaxf(v1, 0.f); }
                    size_t grow = (size_t)(row0 + r);
                    if (LAYER == 1) {
                        *(uint32_t*)&g_A2[grow * 256 + 128 + col] = pack_h2(v0, v1);
                    } else {
                        float2 o; o.x = v0; o.y = v1;
                        *(float2*)&out_ext[grow * 128 + col] = o;
                    }
                }
            }
        }
    }
}

// ==================== entry point ====================
extern "C" void kernel_launch(void* const* d_in, const int* in_sizes, int n_in,
                              void* d_out, int out_size)
{
    (void)n_in; (void)out_size;
    const float* x   = (const float*)d_in[0];
    const void*  ei  = d_in[1];
    const float* W1l = (const float*)d_in[2];
    const float* W1r = (const float*)d_in[3];
    const float* b1  = (const float*)d_in[4];
    const float* W2l = (const float*)d_in[5];
    const float* W2r = (const float*)d_in[6];
    const float* b2  = (const float*)d_in[7];
    float*       out = (float*)d_out;

    int E = in_sizes[1] / 2;
    if (E > E_MAX) E = E_MAX;

    // dynamic smem: W-resident GEMM  (W = 128*(KT+8)*2 B, A = 2*18432 B)
    const int smem1 = 128 * (128 + 8) * 2 + 2 * 18432;   // 71,680 B
    const int smem2 = 128 * (256 + 8) * 2 + 2 * 18432;   // 104,448 B
    cudaFuncSetAttribute(gemm_fp16_kernel<128, true, 1>,
                         cudaFuncAttributeMaxDynamicSharedMemorySize, smem1);
    cudaFuncSetAttribute(gemm_fp16_kernel<256, false, 2>,
                         cudaFuncAttributeMaxDynamicSharedMemorySize, smem2);

    const int agg1_blocks = (((N_NODES + 3) / 4) * 32 + 255) / 256;   // 3125
    const int agg2_blocks = (((N_NODES + 1) / 2) * 32 + 255) / 256;   // 6250

    init_kernel<<<(E + 255) / 256, 256>>>(ei, (const int*)ei, in_sizes[1], E, x,
                                          W1l, W1r, W2l, W2r);              // 0
    scan_kernel<<<NPART, 1024>>>();                                          // 1
    scatter_kernel<<<(E + 255) / 256, 256>>>(ei, E);                         // 2
    agg1_kernel<<<agg1_blocks, 256>>>();                                     // 3 <- profiled
    gemm_fp16_kernel<128, true, 1><<<296, 256, smem1>>>(b1, nullptr);        // 4
    agg2_kernel<<<agg2_blocks, 256>>>();                                     // 5
    gemm_fp16_kernel<256, false, 2><<<148, 256, smem2>>>(b2, out);           // 6
}

// round 16
// speedup vs baseline: 1.0971x; 1.0971x over previous
#include <cuda_runtime.h>
#include <cuda_fp16.h>
#include <cstdint>

#define N_NODES 100000
#define E_MAX   1600000
#define NPART   98          // ceil(100000/1024)
#define XQUADS  (N_NODES * 16)   // x as float4: 100000*64/4 = 1.6M

// ---------------- device scratch (static; zero-init, no dynamic allocation) -----
__device__ int    g_is64;
__device__ int    g_deg[N_NODES];        // zeroed by scatter (prev call) / static
__device__ int    g_offs[N_NODES + 1];
__device__ int    g_cursor[N_NODES];
__device__ int    g_blk_total[NPART];
__device__ int    g_blk_flag[NPART];     // zeroed by scatter (prev call) / static
__device__ int    g_src_sorted[E_MAX];
__device__ __half g_x16[(size_t)N_NODES * 64];    // fp16 copy of x
// fp16 operands:  A1 = [agg1 | x] (stride 128),  A2 = [agg2 | h] (stride 256)
__device__ __half g_A1[(size_t)N_NODES * 128];
__device__ __half g_A2[(size_t)N_NODES * 256];
__device__ __half g_w1[128 * 128];    // [n][k] concat(W1l, W1r)
__device__ __half g_w2[128 * 256];    // [n][k] concat(W2l, W2r)

// ==================== PTX helpers (family-portable) ====================
__device__ __forceinline__ uint32_t smem_u32(const void* p) {
    uint32_t a;
    asm("{ .reg .u64 t; cvta.to.shared.u64 t, %1; cvt.u32.u64 %0, t; }" : "=r"(a) : "l"(p));
    return a;
}
#define LDSM_X4(r0, r1, r2, r3, addr)                                           \
    asm volatile("ldmatrix.sync.aligned.m8n8.x4.shared.b16 {%0,%1,%2,%3}, [%4];" \
                 : "=r"(r0), "=r"(r1), "=r"(r2), "=r"(r3) : "r"(addr))
#define MMA16816F(c, a, b)                                                       \
    asm volatile("mma.sync.aligned.m16n8k16.row.col.f32.f16.f16.f32 "            \
                 "{%0,%1,%2,%3}, {%4,%5,%6,%7}, {%8,%9}, {%0,%1,%2,%3};"         \
                 : "+f"((c)[0]), "+f"((c)[1]), "+f"((c)[2]), "+f"((c)[3])        \
                 : "r"((a)[0]), "r"((a)[1]), "r"((a)[2]), "r"((a)[3]),           \
                   "r"((b)[0]), "r"((b)[1]))
__device__ __forceinline__ void cp16(uint32_t dst, const void* src) {
    asm volatile("cp.async.cg.shared.global [%0], [%1], 16;" :: "r"(dst), "l"(src));
}
#define CP_COMMIT() asm volatile("cp.async.commit_group;" ::: "memory")
#define CP_WAIT1()  asm volatile("cp.async.wait_group 1;" ::: "memory")
#define CP_WAIT0()  asm volatile("cp.async.wait_group 0;" ::: "memory")

__device__ __forceinline__ uint32_t pack_h2(float a, float b) {
    __half2 h = __floats2half2_rn(a, b);
    return *(uint32_t*)&h;
}
__device__ __forceinline__ __half2 u2h(uint32_t u) { return *(__half2*)&u; }
// exact fp32 accumulate of one row (remainders)
__device__ __forceinline__ void acc8(const uint4& p, float* a) {
    float2 f0 = __half22float2(u2h(p.x));
    float2 f1 = __half22float2(u2h(p.y));
    float2 f2 = __half22float2(u2h(p.z));
    float2 f3 = __half22float2(u2h(p.w));
    a[0] += f0.x; a[1] += f0.y; a[2] += f1.x; a[3] += f1.y;
    a[4] += f2.x; a[5] += f2.y; a[6] += f3.x; a[7] += f3.y;
}
// fp16 pairwise tree over 4 rows, fp32 flush (7 ops/word vs 16)
__device__ __forceinline__ void acc8_tree4(const uint4& p0, const uint4& p1,
                                           const uint4& p2, const uint4& p3, float* a) {
    __half2 t; float2 f;
    t = __hadd2(__hadd2(u2h(p0.x), u2h(p1.x)), __hadd2(u2h(p2.x), u2h(p3.x)));
    f = __half22float2(t); a[0] += f.x; a[1] += f.y;
    t = __hadd2(__hadd2(u2h(p0.y), u2h(p1.y)), __hadd2(u2h(p2.y), u2h(p3.y)));
    f = __half22float2(t); a[2] += f.x; a[3] += f.y;
    t = __hadd2(__hadd2(u2h(p0.z), u2h(p1.z)), __hadd2(u2h(p2.z), u2h(p3.z)));
    f = __half22float2(t); a[4] += f.x; a[5] += f.y;
    t = __hadd2(__hadd2(u2h(p0.w), u2h(p1.w)), __hadd2(u2h(p2.w), u2h(p3.w)));
    f = __half22float2(t); a[6] += f.x; a[7] += f.y;
}

// ==================== launch 0: init (detect + weights + x->fp16 + A1 self + HIST)
__global__ void init_kernel(const void* __restrict__ ei, const int* __restrict__ ei32,
                            int n_words, int E,
                            const float* __restrict__ x,
                            const float* __restrict__ W1l, const float* __restrict__ W1r,
                            const float* __restrict__ W2l, const float* __restrict__ W2r) {
    __shared__ int s_is64;
    int idx = blockIdx.x * blockDim.x + threadIdx.x;
    if (threadIdx.x < 32) {
        int lane = threadIdx.x;
        int wi = 1 + 2 * lane;
        int z = (wi < n_words && ei32[wi] == 0) ? 1 : 0;
        unsigned m = __ballot_sync(0xffffffffu, z);
        if (lane == 0) {
            s_is64 = (__popc(m) > 24) ? 1 : 0;
            if (blockIdx.x == 0) g_is64 = s_is64;
        }
    }
    __syncthreads();
    int is64 = s_is64;
    if (idx < E) {
        int d = is64 ? (int)((const long long*)ei)[(size_t)E + idx]
                     : ((const int*)ei)[(size_t)E + idx];
        if ((unsigned)d < (unsigned)N_NODES) atomicAdd(&g_deg[d], 1);
    }
    if (idx < 128 * 128) {                       // layer 1 weights: Ktot=128, Kh=64
        int n = idx >> 7, k = idx & 127;
        float v = (k < 64) ? W1l[n * 64 + k] : W1r[n * 64 + (k - 64)];
        g_w1[idx] = __float2half_rn(v);
    } else if (idx < 128 * 128 + 128 * 256) {    // layer 2 weights: Ktot=256, Kh=128
        int j = idx - 128 * 128;
        int n = j >> 8, k = j & 255;
        float v = (k < 128) ? W2l[n * 128 + k] : W2r[n * 128 + (k - 128)];
        g_w2[j] = __float2half_rn(v);
    }
    if (idx < XQUADS) {                          // x -> fp16 (per float4) + A1 self cols
        float4 v = *(const float4*)&x[(size_t)idx * 4];
        uint2 o;
        o.x = pack_h2(v.x, v.y);
        o.y = pack_h2(v.z, v.w);
        *(uint2*)&g_x16[(size_t)idx * 4] = o;
        int m = idx >> 4, c4 = (idx & 15) * 4;
        *(uint2*)&g_A1[(size_t)m * 128 + 64 + c4] = o;   // A1 cols 64..127 = x16
    }
}

// ==================== launch 1: single-pass scan (decoupled lookback) ===========
__global__ void scan_kernel() {
    __shared__ int s_woff[32];
    __shared__ int s_red[4];
    __shared__ int s_pred;
    int tid = threadIdx.x, lane = tid & 31, wid = tid >> 5;
    int bid = blockIdx.x;
    int i = bid * 1024 + tid;
    int v = (i < N_NODES) ? g_deg[i] : 0;
    int inc = v;
#pragma unroll
    for (int o = 1; o < 32; o <<= 1) {
        int t = __shfl_up_sync(0xffffffffu, inc, o);
        if (lane >= o) inc += t;
    }
    if (lane == 31) s_woff[wid] = inc;
    __syncthreads();
    if (wid == 0) {
        int ws = s_woff[lane];
        int wi = ws;
#pragma unroll
        for (int o = 1; o < 32; o <<= 1) {
            int t = __shfl_up_sync(0xffffffffu, wi, o);
            if (lane >= o) wi += t;
        }
        s_woff[lane] = wi - ws;
    }
    __syncthreads();
    int excl = s_woff[wid] + inc - v;
    if (tid == 1023) {
        g_blk_total[bid] = excl + v;
        __threadfence();
        atomicExch(&g_blk_flag[bid], 1);
    }
    int myp = 0;
    if (tid < bid) {
        while (atomicAdd(&g_blk_flag[tid], 0) == 0) {}
        myp = atomicAdd(&g_blk_total[tid], 0);
    }
    if (tid < 128) {
#pragma unroll
        for (int o = 16; o > 0; o >>= 1)
            myp += __shfl_xor_sync(0xffffffffu, myp, o);
        if (lane == 0) s_red[wid] = myp;
    }
    __syncthreads();
    if (tid == 0) s_pred = s_red[0] + s_red[1] + s_red[2] + s_red[3];
    __syncthreads();
    int off = s_pred;
    if (i < N_NODES) {
        int o = excl + off;
        g_offs[i] = o;
        g_cursor[i] = o;
    }
    if (bid == NPART - 1 && tid == 1023) g_offs[N_NODES] = off + excl + v;
}

// ==================== launch 2: scatter (+ cleanup for next call) ===============
__global__ void scatter_kernel(const void* __restrict__ ei, int E) {
    int e = blockIdx.x * blockDim.x + threadIdx.x;
    int is64 = g_is64;
    if (e < E) {
        int d, s;
        if (is64) {
            d = (int)((const long long*)ei)[(size_t)E + e];
            s = (int)((const long long*)ei)[(size_t)e];
        } else {
            d = ((const int*)ei)[(size_t)E + e];
            s = ((const int*)ei)[(size_t)e];
        }
        if ((unsigned)d < (unsigned)N_NODES && (unsigned)s < (unsigned)N_NODES) {
            int p = atomicAdd(&g_cursor[d], 1);
            g_src_sorted[p] = s;
        }
    }
    if (e < N_NODES) g_deg[e] = 0;
    if (e < NPART) g_blk_flag[e] = 0;
}

// ==================== aggregation: node-per-group, fp16 tree4 (round-13 form) ===
// agg1: warp = 4 nodes; group of 8 lanes owns one node (lane's 16B = 8 features).
__global__ void agg1_kernel() {
    int gt = blockIdx.x * blockDim.x + threadIdx.x;
    int warp = gt >> 5, lane = threadIdx.x & 31;
    int grp = lane >> 3, gl = lane & 7;
    int w = warp * 4 + grp;
    if (w >= N_NODES) return;
    int beg = g_offs[w], end = g_offs[w + 1];
    float inv = 1.0f / (float)max(end - beg, 1);
    float a[8] = {0.f, 0.f, 0.f, 0.f, 0.f, 0.f, 0.f, 0.f};
    int e = beg;
    for (; e + 3 < end; e += 4) {
        int s0 = g_src_sorted[e];
        int s1 = g_src_sorted[e + 1];
        int s2 = g_src_sorted[e + 2];
        int s3 = g_src_sorted[e + 3];
        uint4 p0 = *(const uint4*)&g_x16[(size_t)s0 * 64 + gl * 8];
        uint4 p1 = *(const uint4*)&g_x16[(size_t)s1 * 64 + gl * 8];
        uint4 p2 = *(const uint4*)&g_x16[(size_t)s2 * 64 + gl * 8];
        uint4 p3 = *(const uint4*)&g_x16[(size_t)s3 * 64 + gl * 8];
        acc8_tree4(p0, p1, p2, p3, a);
    }
    for (; e < end; e++) {
        int ss = g_src_sorted[e];
        uint4 p = *(const uint4*)&g_x16[(size_t)ss * 64 + gl * 8];
        acc8(p, a);
    }
    uint4 o;
    o.x = pack_h2(a[0] * inv, a[1] * inv);
    o.y = pack_h2(a[2] * inv, a[3] * inv);
    o.z = pack_h2(a[4] * inv, a[5] * inv);
    o.w = pack_h2(a[6] * inv, a[7] * inv);
    *(uint4*)&g_A1[(size_t)w * 128 + gl * 8] = o;
    // self part (cols 64..127) written by init_kernel
}
// agg2: warp = 2 nodes; group of 16 lanes owns one node.
__global__ void agg2_kernel() {
    int gt = blockIdx.x * blockDim.x + threadIdx.x;
    int warp = gt >> 5, lane = threadIdx.x & 31;
    int grp = lane >> 4, gl = lane & 15;
    int w = warp * 2 + grp;
    if (w >= N_NODES) return;
    int beg = g_offs[w], end = g_offs[w + 1];
    float inv = 1.0f / (float)max(end - beg, 1);
    float a[8] = {0.f, 0.f, 0.f, 0.f, 0.f, 0.f, 0.f, 0.f};
    int e = beg;
    for (; e + 3 < end; e += 4) {
        int s0 = g_src_sorted[e];
        int s1 = g_src_sorted[e + 1];
        int s2 = g_src_sorted[e + 2];
        int s3 = g_src_sorted[e + 3];
        uint4 p0 = *(const uint4*)&g_A2[(size_t)s0 * 256 + 128 + gl * 8];
        uint4 p1 = *(const uint4*)&g_A2[(size_t)s1 * 256 + 128 + gl * 8];
        uint4 p2 = *(const uint4*)&g_A2[(size_t)s2 * 256 + 128 + gl * 8];
        uint4 p3 = *(const uint4*)&g_A2[(size_t)s3 * 256 + 128 + gl * 8];
        acc8_tree4(p0, p1, p2, p3, a);
    }
    for (; e < end; e++) {
        int ss = g_src_sorted[e];
        uint4 p = *(const uint4*)&g_A2[(size_t)ss * 256 + 128 + gl * 8];
        acc8(p, a);
    }
    uint4 o;
    o.x = pack_h2(a[0] * inv, a[1] * inv);
    o.y = pack_h2(a[2] * inv, a[3] * inv);
    o.z = pack_h2(a[4] * inv, a[5] * inv);
    o.w = pack_h2(a[6] * inv, a[7] * inv);
    *(uint4*)&g_A2[(size_t)w * 256 + gl * 8] = o;
}

// ==================== cp.async pipelined fp16 mma GEMM (BK=32, round-13 form) ===
template <int KT, bool RELU, int LAYER>
__global__ __launch_bounds__(256) void gemm_fp16_kernel(
    const float* __restrict__ bias, float* __restrict__ out_ext)
{
    constexpr int NCH = KT / 32;
    constexpr int RS = 40;
    constexpr uint32_t ARR_B = 128 * RS * 2;      // 10240 B per array
    constexpr uint32_t STG_B = 2 * ARR_B;         // A + W per stage
    __shared__ __align__(16) __half sbuf[2][2][128 * RS];   // 40 KB

    const __half* A = (LAYER == 1) ? g_A1 : g_A2;
    const __half* W = (LAYER == 1) ? g_w1 : g_w2;

    const int tid = threadIdx.x, lane = tid & 31, wid = tid >> 5;
    const int row0 = blockIdx.x * 128;
    const int valid = min(128, N_NODES - row0);
    const int wr = wid & 3, wc = wid >> 2;

    float c[2][8][4];
#pragma unroll
    for (int mi = 0; mi < 2; mi++)
#pragma unroll
        for (int ni = 0; ni < 8; ni++)
#pragma unroll
            for (int q = 0; q < 4; q++) c[mi][ni][q] = 0.f;

    const uint32_t sb0 = smem_u32(sbuf);

    const int ld_r = tid >> 1;
    const int ld_u = (tid & 1) * 2;
    const int ar = min(row0 + ld_r, N_NODES - 1);
    const size_t goA = (size_t)ar * KT + ld_u * 8;
    const size_t goW = (size_t)ld_r * KT + ld_u * 8;
    const uint32_t dst_ru = (uint32_t)(ld_r * RS + ld_u * 8) * 2;

    const int a_m = ((lane >> 3) & 1) * 8 + (lane & 7);
    const int a_u = (lane >> 4);
    const int b_n = ((lane >> 4) << 3) + (lane & 7);
    const int b_u = ((lane >> 3) & 1);

    {
        uint32_t d = sb0 + dst_ru;
        cp16(d, &A[goA]);            cp16(d + 16, &A[goA + 8]);
        cp16(d + ARR_B, &W[goW]);    cp16(d + ARR_B + 16, &W[goW + 8]);
        CP_COMMIT();
    }

    for (int kc = 0; kc < NCH; kc++) {
        if (kc + 1 < NCH) {
            uint32_t d = sb0 + ((kc + 1) & 1) * STG_B + dst_ru;
            size_t ko = (size_t)(kc + 1) * 32;
            cp16(d, &A[goA + ko]);            cp16(d + 16, &A[goA + ko + 8]);
            cp16(d + ARR_B, &W[goW + ko]);    cp16(d + ARR_B + 16, &W[goW + ko + 8]);
            CP_COMMIT();
            CP_WAIT1();
        } else {
            CP_WAIT0();
        }
        __syncthreads();

        const uint32_t sa = sb0 + (kc & 1) * STG_B;
        const uint32_t sw = sa + ARR_B;

#pragma unroll
        for (int ks = 0; ks < 2; ks++) {
            uint32_t af[2][4], bf[8][2];
#pragma unroll
            for (int mi = 0; mi < 2; mi++) {
                int rr = wr * 32 + mi * 16 + a_m;
                uint32_t off = (uint32_t)(rr * RS + (ks * 2 + a_u) * 8) * 2;
                LDSM_X4(af[mi][0], af[mi][1], af[mi][2], af[mi][3], sa + off);
            }
#pragma unroll
            for (int nj = 0; nj < 4; nj++) {
                int nr = wc * 64 + nj * 16 + b_n;
                uint32_t off = (uint32_t)(nr * RS + (ks * 2 + b_u) * 8) * 2;
                LDSM_X4(bf[nj * 2][0], bf[nj * 2][1], bf[nj * 2 + 1][0], bf[nj * 2 + 1][1], sw + off);
            }
#pragma unroll
            for (int mi = 0; mi < 2; mi++)
#pragma unroll
                for (int ni = 0; ni < 8; ni++)
                    MMA16816F(c[mi][ni], af[mi], bf[ni]);
        }
        __syncthreads();
    }

    // ---- epilogue: bias + (relu); layer1 -> h (fp16) into A2 cols 128..255 ----
    const int g = lane >> 2, tg = lane & 3;
#pragma unroll
    for (int ni = 0; ni < 8; ni++) {
        int col = wc * 64 + ni * 8 + tg * 2;
        float2 bv = *(const float2*)&bias[col];
#pragma unroll
        for (int mi = 0; mi < 2; mi++) {
            int rl = wr * 32 + mi * 16 + g;
#pragma unroll
            for (int hrow = 0; hrow < 2; hrow++) {
                int r = rl + hrow * 8;
                if (r >= valid) continue;
                float v0 = c[mi][ni][hrow * 2 + 0] + bv.x;
                float v1 = c[mi][ni][hrow * 2 + 1] + bv.y;
                if (RELU) { v0 = fmaxf(v0, 0.f); v1 = fmaxf(v1, 0.f); }
                size_t grow = (size_t)(row0 + r);
                if (LAYER == 1) {
                    *(uint32_t*)&g_A2[grow * 256 + 128 + col] = pack_h2(v0, v1);
                } else {
                    float2 o; o.x = v0; o.y = v1;
                    *(float2*)&out_ext[grow * 128 + col] = o;
                }
            }
        }
    }
}

// ==================== entry point ====================
extern "C" void kernel_launch(void* const* d_in, const int* in_sizes, int n_in,
                              void* d_out, int out_size)
{
    (void)n_in; (void)out_size;
    const float* x   = (const float*)d_in[0];
    const void*  ei  = d_in[1];
    const float* W1l = (const float*)d_in[2];
    const float* W1r = (const float*)d_in[3];
    const float* b1  = (const float*)d_in[4];
    const float* W2l = (const float*)d_in[5];
    const float* W2r = (const float*)d_in[6];
    const float* b2  = (const float*)d_in[7];
    float*       out = (float*)d_out;

    int E = in_sizes[1] / 2;
    if (E > E_MAX) E = E_MAX;

    const int agg1_blocks = (((N_NODES + 3) / 4) * 32 + 255) / 256;   // 3125
    const int agg2_blocks = (((N_NODES + 1) / 2) * 32 + 255) / 256;   // 6250
    const int gemm_blocks = (N_NODES + 127) / 128;                    // 782

    init_kernel<<<(E + 255) / 256, 256>>>(ei, (const int*)ei, in_sizes[1], E, x,
                                          W1l, W1r, W2l, W2r);         // 0
    scan_kernel<<<NPART, 1024>>>();                                     // 1
    scatter_kernel<<<(E + 255) / 256, 256>>>(ei, E);                    // 2
    agg1_kernel<<<agg1_blocks, 256>>>();                                // 3 <- profiled
    gemm_fp16_kernel<128, true, 1><<<gemm_blocks, 256>>>(b1, nullptr);  // 4
    agg2_kernel<<<agg2_blocks, 256>>>();                                // 5
    gemm_fp16_kernel<256, false, 2><<<gemm_blocks, 256>>>(b2, out);     // 6
}